// round 7
// baseline (speedup 1.0000x reference)
#include <cuda_runtime.h>
#include <cstdint>

// Problem constants
#define BB 32
#define II 4096
#define VV 512
#define VTILE 128          // v per CTA (M)
#define CTA_I 32           // i per CTA  -> K = 256
#define STAGE_I 2          // i per stage -> K = 16
#define NS (CTA_I/STAGE_I) // 16 stages
#define NSTAGE 3           // pipeline ring depth
#define NCHUNK (II/CTA_I)  // 128 k-splits
#define NRED 8
#define NTHREADS 256
#define ASTRIDE 20         // floats per A row (16 data + 4 pad): conflict-free frags
#define BSTRIDE 20

__device__ float g_part[NCHUNK][BB * VV];   // split-K partials (8 MB)
__device__ float g_red[NRED][BB * VV];      // second-stage partials

__device__ __forceinline__ void cp_async16(void* smem_dst, const void* gmem_src) {
    unsigned s = (unsigned)__cvta_generic_to_shared(smem_dst);
    asm volatile("cp.async.cg.shared.global [%0], [%1], 16;"
                 :: "r"(s), "l"(gmem_src));
}
__device__ __forceinline__ void cp_commit() {
    asm volatile("cp.async.commit_group;" ::: "memory");
}
__device__ __forceinline__ void cp_wait1() {
    asm volatile("cp.async.wait_group 1;" ::: "memory");
}
__device__ __forceinline__ void cp_wait0() {
    asm volatile("cp.async.wait_group 0;" ::: "memory");
}

// tf32 split: hi = top 19 bits (valid tf32); lo = masked remainder
__device__ __forceinline__ uint32_t tf32_hi(float f) {
    return __float_as_uint(f) & 0xFFFFE000u;
}
__device__ __forceinline__ uint32_t tf32_lo(float f, uint32_t hi) {
    return __float_as_uint(f - __uint_as_float(hi)) & 0xFFFFE000u;
}

__device__ __forceinline__ void mma_tf32(float* c, const uint32_t* a,
                                         const uint32_t* b) {
    asm volatile(
        "mma.sync.aligned.m16n8k8.row.col.f32.tf32.tf32.f32 "
        "{%0,%1,%2,%3}, {%4,%5,%6,%7}, {%8,%9}, {%0,%1,%2,%3};"
        : "+f"(c[0]), "+f"(c[1]), "+f"(c[2]), "+f"(c[3])
        : "r"(a[0]), "r"(a[1]), "r"(a[2]), "r"(a[3]), "r"(b[0]), "r"(b[1]));
}

// D[v_local, b] = sum_k A[v_local,k] * B[k,b];  A = W chunk, B = x chunk (K=256)
__global__ void __launch_bounds__(NTHREADS)
caps_mma_kernel(const float4* __restrict__ x4, const float4* __restrict__ w4) {
    __shared__ float Asm[NSTAGE][VTILE * ASTRIDE];  // 3 x 10 KB
    __shared__ float Bsm[NSTAGE][BB * BSTRIDE];     // 3 x 2.5 KB

    const int tid  = threadIdx.x;
    const int w    = tid >> 5;        // warp 0..7 -> m rows [w*16, w*16+16)
    const int lane = tid & 31;
    const int g    = lane >> 2;       // groupID 0..7
    const int t    = lane & 3;        // threadID-in-group 0..3
    const int v0   = blockIdx.x * VTILE;
    const int i0   = blockIdx.y * CTA_I;

    // A staging: 512 float4/stage -> 2 per thread
    const int a_v    = tid >> 1;      // 0..127
    const int a_half = tid & 1;
    // B staging: 128 float4/stage -> tid<128, 1 each
    const int b_b    = tid >> 2;      // 0..31 (tid<128)
    const int b_il   = (tid >> 1) & 1;
    const int b_h    = tid & 1;

    float c[4][4];
    #pragma unroll
    for (int nt = 0; nt < 4; ++nt)
        #pragma unroll
        for (int j = 0; j < 4; ++j) c[nt][j] = 0.f;

    auto load_stage = [&](int s, int buf) {
        const int ib = i0 + s * STAGE_I;
        #pragma unroll
        for (int il = 0; il < 2; ++il)
            cp_async16(&Asm[buf][a_v * ASTRIDE + il * 8 + a_half * 4],
                       &w4[((size_t)(ib + il) * 512 + v0 + a_v) * 2 + a_half]);
        if (tid < 128)
            cp_async16(&Bsm[buf][b_b * BSTRIDE + b_il * 8 + b_h * 4],
                       &x4[(size_t)b_b * 8192 + (size_t)(ib + b_il) * 2 + b_h]);
    };

    load_stage(0, 0); cp_commit();
    load_stage(1, 1); cp_commit();

    for (int s = 0; s < NS; ++s) {
        const int buf = s % NSTAGE;
        if (s + 1 < NS) cp_wait1(); else cp_wait0();   // stage s resident (this thread)
        __syncthreads();                               // all threads' stage s visible;
                                                       // also: compute(s-1) done everywhere
        if (s + 2 < NS) {                              // refill the buffer freed at s-1
            load_stage(s + 2, (s + 2) % NSTAGE);
            cp_commit();
        }

        #pragma unroll
        for (int ks = 0; ks < 2; ++ks) {
            // A fragment (m16 k8): rows w*16+g, +8; cols ks*8+t, +4
            const float* ap = &Asm[buf][(w * 16 + g) * ASTRIDE + ks * 8 + t];
            float af[4] = { ap[0], ap[8 * ASTRIDE], ap[4], ap[8 * ASTRIDE + 4] };
            uint32_t ah[4], al[4];
            #pragma unroll
            for (int j = 0; j < 4; ++j) {
                ah[j] = tf32_hi(af[j]);
                al[j] = tf32_lo(af[j], ah[j]);
            }
            #pragma unroll
            for (int nt = 0; nt < 4; ++nt) {
                // B fragment (k8 n8): col n = nt*8+g (b), rows k = ks*8+t, +4
                const float* bp = &Bsm[buf][(nt * 8 + g) * BSTRIDE + ks * 8 + t];
                float bf0 = bp[0], bf1 = bp[4];
                uint32_t bh[2], bl[2];
                bh[0] = tf32_hi(bf0); bl[0] = tf32_lo(bf0, bh[0]);
                bh[1] = tf32_hi(bf1); bl[1] = tf32_lo(bf1, bh[1]);
                mma_tf32(c[nt], ah, bh);
                mma_tf32(c[nt], ah, bl);
                mma_tf32(c[nt], al, bh);
            }
        }
    }

    // ---- epilogue: scatter accumulators to split-K partials ----
    float* outp = &g_part[blockIdx.y][0];
    const int row = w * 16 + g;
    #pragma unroll
    for (int nt = 0; nt < 4; ++nt) {
        const int bc = nt * 8 + t * 2;
        outp[(size_t)bc * VV + v0 + row]           = c[nt][0];
        outp[(size_t)(bc + 1) * VV + v0 + row]     = c[nt][1];
        outp[(size_t)bc * VV + v0 + row + 8]       = c[nt][2];
        outp[(size_t)(bc + 1) * VV + v0 + row + 8] = c[nt][3];
    }
}

// First-stage reduction: 256 blocks, each folds 16 chunks for one b.
__global__ void __launch_bounds__(256)
caps_reduce_kernel() {
    const int b   = blockIdx.x;   // 0..31
    const int s   = blockIdx.y;   // 0..7
    const int tid = threadIdx.x;
    #pragma unroll
    for (int j = 0; j < 2; ++j) {
        const int v = tid + j * 256;
        float acc = 0.f;
        #pragma unroll
        for (int cc = 0; cc < NCHUNK / NRED; ++cc)
            acc += g_part[s * (NCHUNK / NRED) + cc][b * VV + v];
        g_red[s][b * VV + v] = acc;
    }
}

// Final: fold 8 partials, squash, write (t, outputs) — identical halves.
__global__ void __launch_bounds__(256)
caps_finish_kernel(float* __restrict__ out, int out_size) {
    const int b   = blockIdx.x;
    const int tid = threadIdx.x;
    __shared__ float red[256];

    float local[2];
    #pragma unroll
    for (int j = 0; j < 2; ++j) {
        const int v = tid + j * 256;
        float acc = 0.f;
        #pragma unroll
        for (int cc = 0; cc < NRED; ++cc) acc += g_red[cc][b * VV + v];
        local[j] = acc;
    }

    float sq = local[0] * local[0] + local[1] * local[1];
    red[tid] = sq;
    __syncthreads();
    for (int off = 128; off; off >>= 1) {
        if (tid < off) red[tid] += red[tid + off];
        __syncthreads();
    }
    const float total = red[0];
    const float scale = total / ((1.0f + total) * sqrtf(total));

    #pragma unroll
    for (int j = 0; j < 2; ++j) {
        const int v   = tid + j * 256;
        const float o = local[j] * scale;
        const int idx = b * VV + v;
        if (idx < out_size) out[idx] = o;                       // t
        if (idx + BB * VV < out_size) out[idx + BB * VV] = o;   // outputs
    }
}

extern "C" void kernel_launch(void* const* d_in, const int* in_sizes, int n_in,
                              void* d_out, int out_size) {
    const float4* x4 = (const float4*)d_in[0];  // x: [32, 4096, 8] fp32
    const float4* w4 = (const float4*)d_in[1];  // W: [1, 4096, 512, 8] fp32
    float* out = (float*)d_out;

    dim3 grid1(VV / VTILE, NCHUNK);  // (4, 128) = 512 CTAs
    caps_mma_kernel<<<grid1, NTHREADS>>>(x4, w4);
    caps_reduce_kernel<<<dim3(BB, NRED), 256>>>();
    caps_finish_kernel<<<BB, 256>>>(out, out_size);
}

// round 8
// speedup vs baseline: 1.1508x; 1.1508x over previous
#include <cuda_runtime.h>
#include <cstdint>

// Problem constants
#define BB 32
#define II 4096
#define VV 512
#define VTILE 128          // v per CTA (M)
#define CTA_I 16           // i per CTA  -> K = 128
#define STAGE_I 4          // i per stage -> K = 32
#define NS (CTA_I/STAGE_I) // 4 stages
#define NCHUNK (II/CTA_I)  // 256 k-splits
#define NRED 16
#define NTHREADS 256
#define ASTRIDE 36         // floats per A row (32 data + 4 pad): conflict-free frags
#define BSTRIDE 36

__device__ float g_part[NCHUNK][BB * VV];   // split-K partials (16 MB)
__device__ float g_red[NRED][BB * VV];      // second-stage partials

__device__ __forceinline__ void cp_async16(void* smem_dst, const void* gmem_src) {
    unsigned s = (unsigned)__cvta_generic_to_shared(smem_dst);
    asm volatile("cp.async.cg.shared.global [%0], [%1], 16;"
                 :: "r"(s), "l"(gmem_src));
}
__device__ __forceinline__ void cp_commit() {
    asm volatile("cp.async.commit_group;" ::: "memory");
}
__device__ __forceinline__ void cp_wait1() {
    asm volatile("cp.async.wait_group 1;" ::: "memory");
}
__device__ __forceinline__ void cp_wait0() {
    asm volatile("cp.async.wait_group 0;" ::: "memory");
}

// tf32 split: hi = top 19 bits (valid tf32); lo = masked remainder
__device__ __forceinline__ uint32_t tf32_hi(float f) {
    return __float_as_uint(f) & 0xFFFFE000u;
}
__device__ __forceinline__ uint32_t tf32_lo(float f, uint32_t hi) {
    return __float_as_uint(f - __uint_as_float(hi)) & 0xFFFFE000u;
}

__device__ __forceinline__ void mma_tf32(float* c, const uint32_t* a,
                                         const uint32_t* b) {
    asm volatile(
        "mma.sync.aligned.m16n8k8.row.col.f32.tf32.tf32.f32 "
        "{%0,%1,%2,%3}, {%4,%5,%6,%7}, {%8,%9}, {%0,%1,%2,%3};"
        : "+f"(c[0]), "+f"(c[1]), "+f"(c[2]), "+f"(c[3])
        : "r"(a[0]), "r"(a[1]), "r"(a[2]), "r"(a[3]), "r"(b[0]), "r"(b[1]));
}

// D[v_local, b] = sum_k A[v_local,k] * B[k,b];  A = W chunk, B = x chunk (K=128)
__global__ void __launch_bounds__(NTHREADS, 2)
caps_mma_kernel(const float4* __restrict__ x4, const float4* __restrict__ w4) {
    __shared__ float Asm[2][VTILE * ASTRIDE];  // 2 x 18 KB
    __shared__ float Bsm[2][BB * BSTRIDE];     // 2 x 4.5 KB

    const int tid  = threadIdx.x;
    const int w    = tid >> 5;        // warp 0..7 -> m rows [w*16, w*16+16)
    const int lane = tid & 31;
    const int g    = lane >> 2;       // groupID 0..7
    const int t    = lane & 3;        // threadID-in-group 0..3
    const int v0   = blockIdx.x * VTILE;
    const int i0   = blockIdx.y * CTA_I;

    // A staging indices: 1024 16B-chunks/stage, 4 per thread (i_local = k-iter)
    const int a_half = tid & 1;
    const int a_v    = (tid >> 1) & 127;
    // B staging indices: 256 chunks/stage, 1 per thread
    const int b_half = tid & 1;
    const int b_il   = (tid >> 1) & 3;
    const int b_b    = tid >> 3;

    float c[4][4];
    #pragma unroll
    for (int nt = 0; nt < 4; ++nt)
        #pragma unroll
        for (int j = 0; j < 4; ++j) c[nt][j] = 0.f;

    auto load_stage = [&](int s, int buf) {
        const int ib = i0 + s * STAGE_I;
        #pragma unroll
        for (int k = 0; k < 4; ++k) {  // i_local = k
            cp_async16(&Asm[buf][a_v * ASTRIDE + k * 8 + a_half * 4],
                       &w4[((size_t)(ib + k) * 512 + v0 + a_v) * 2 + a_half]);
        }
        cp_async16(&Bsm[buf][b_b * BSTRIDE + b_il * 8 + b_half * 4],
                   &x4[(size_t)b_b * 8192 + (size_t)(ib + b_il) * 2 + b_half]);
    };

    load_stage(0, 0);
    cp_commit();

    for (int s = 0; s < NS; ++s) {
        const int buf = s & 1;
        if (s + 1 < NS) {
            load_stage(s + 1, buf ^ 1);
            cp_commit();
            cp_wait1();
        } else {
            cp_wait0();
        }
        __syncthreads();

        #pragma unroll
        for (int ks = 0; ks < 4; ++ks) {
            // A fragment (m16 k8): rows w*16+g, +8; cols ks*8+t, +4
            const float* ap = &Asm[buf][(w * 16 + g) * ASTRIDE + ks * 8 + t];
            float af[4] = { ap[0], ap[8 * ASTRIDE], ap[4], ap[8 * ASTRIDE + 4] };
            uint32_t ah[4], al[4];
            #pragma unroll
            for (int j = 0; j < 4; ++j) {
                ah[j] = tf32_hi(af[j]);
                al[j] = tf32_lo(af[j], ah[j]);
            }
            #pragma unroll
            for (int nt = 0; nt < 4; ++nt) {
                // B fragment (k8 n8): col n = nt*8+g (b), rows k = ks*8+t, +4
                const float* bp = &Bsm[buf][(nt * 8 + g) * BSTRIDE + ks * 8 + t];
                float bf0 = bp[0], bf1 = bp[4];
                uint32_t bh[2], bl[2];
                bh[0] = tf32_hi(bf0); bl[0] = tf32_lo(bf0, bh[0]);
                bh[1] = tf32_hi(bf1); bl[1] = tf32_lo(bf1, bh[1]);
                mma_tf32(c[nt], ah, bh);
                mma_tf32(c[nt], ah, bl);
                mma_tf32(c[nt], al, bh);
            }
        }
        __syncthreads();
    }

    // ---- epilogue: scatter accumulators to split-K partials ----
    float* outp = &g_part[blockIdx.y][0];
    const int row = w * 16 + g;
    #pragma unroll
    for (int nt = 0; nt < 4; ++nt) {
        const int bc = nt * 8 + t * 2;
        outp[(size_t)bc * VV + v0 + row]           = c[nt][0];
        outp[(size_t)(bc + 1) * VV + v0 + row]     = c[nt][1];
        outp[(size_t)bc * VV + v0 + row + 8]       = c[nt][2];
        outp[(size_t)(bc + 1) * VV + v0 + row + 8] = c[nt][3];
    }
}

// First-stage reduction: 512 blocks, each folds 16 chunks for one b.
__global__ void __launch_bounds__(256)
caps_reduce_kernel() {
    const int b   = blockIdx.x;   // 0..31
    const int s   = blockIdx.y;   // 0..NRED-1
    const int tid = threadIdx.x;
    #pragma unroll
    for (int j = 0; j < 2; ++j) {
        const int v = tid + j * 256;
        float acc = 0.f;
        #pragma unroll
        for (int cc = 0; cc < NCHUNK / NRED; ++cc)
            acc += g_part[s * (NCHUNK / NRED) + cc][b * VV + v];
        g_red[s][b * VV + v] = acc;
    }
}

// Final: fold NRED partials, squash, write (t, outputs) — identical halves.
__global__ void __launch_bounds__(256)
caps_finish_kernel(float* __restrict__ out, int out_size) {
    const int b   = blockIdx.x;
    const int tid = threadIdx.x;
    __shared__ float red[256];

    float local[2];
    #pragma unroll
    for (int j = 0; j < 2; ++j) {
        const int v = tid + j * 256;
        float acc = 0.f;
        #pragma unroll
        for (int cc = 0; cc < NRED; ++cc) acc += g_red[cc][b * VV + v];
        local[j] = acc;
    }

    float sq = local[0] * local[0] + local[1] * local[1];
    red[tid] = sq;
    __syncthreads();
    for (int off = 128; off; off >>= 1) {
        if (tid < off) red[tid] += red[tid + off];
        __syncthreads();
    }
    const float total = red[0];
    const float scale = total / ((1.0f + total) * sqrtf(total));

    #pragma unroll
    for (int j = 0; j < 2; ++j) {
        const int v   = tid + j * 256;
        const float o = local[j] * scale;
        const int idx = b * VV + v;
        if (idx < out_size) out[idx] = o;                       // t
        if (idx + BB * VV < out_size) out[idx + BB * VV] = o;   // outputs
    }
}

extern "C" void kernel_launch(void* const* d_in, const int* in_sizes, int n_in,
                              void* d_out, int out_size) {
    const float4* x4 = (const float4*)d_in[0];  // x: [32, 4096, 8] fp32
    const float4* w4 = (const float4*)d_in[1];  // W: [1, 4096, 512, 8] fp32
    float* out = (float*)d_out;

    dim3 grid1(VV / VTILE, NCHUNK);  // (4, 256) = 1024 CTAs
    caps_mma_kernel<<<grid1, NTHREADS>>>(x4, w4);
    caps_reduce_kernel<<<dim3(BB, NRED), 256>>>();
    caps_finish_kernel<<<BB, 256>>>(out, out_size);
}

// round 9
// speedup vs baseline: 1.9583x; 1.7018x over previous
#include <cuda_runtime.h>
#include <cstdint>

// Problem constants
#define BB 32
#define II 4096
#define VV 512
#define VTILE 128          // v per CTA (M)
#define CTA_I 32           // i per CTA -> K = 256
#define NCHUNK (II/CTA_I)  // 128 k-splits
#define NRED 8
#define NTHREADS 256
#define BSTRIDE 260        // floats per B row (256 data + 4 pad): conflict-free

__device__ float g_part[NCHUNK][BB * VV];   // split-K partials (8 MB)
__device__ float g_red[NRED][BB * VV];      // second-stage partials

__device__ __forceinline__ void cp_async16(void* smem_dst, const void* gmem_src) {
    unsigned s = (unsigned)__cvta_generic_to_shared(smem_dst);
    asm volatile("cp.async.cg.shared.global [%0], [%1], 16;"
                 :: "r"(s), "l"(gmem_src));
}
__device__ __forceinline__ void cp_commit() {
    asm volatile("cp.async.commit_group;" ::: "memory");
}
__device__ __forceinline__ void cp_wait0() {
    asm volatile("cp.async.wait_group 0;" ::: "memory");
}

// tf32 split: hi = top 19 bits (valid tf32); lo = masked remainder
__device__ __forceinline__ uint32_t tf32_hi(float f) {
    return __float_as_uint(f) & 0xFFFFE000u;
}
__device__ __forceinline__ uint32_t tf32_lo(float f, uint32_t hi) {
    return __float_as_uint(f - __uint_as_float(hi)) & 0xFFFFE000u;
}

__device__ __forceinline__ void mma_tf32(float* c, const uint32_t* a,
                                         const uint32_t* b) {
    asm volatile(
        "mma.sync.aligned.m16n8k8.row.col.f32.tf32.tf32.f32 "
        "{%0,%1,%2,%3}, {%4,%5,%6,%7}, {%8,%9}, {%0,%1,%2,%3};"
        : "+f"(c[0]), "+f"(c[1]), "+f"(c[2]), "+f"(c[3])
        : "r"(a[0]), "r"(a[1]), "r"(a[2]), "r"(a[3]), "r"(b[0]), "r"(b[1]));
}

// D[v_local, b] = sum_k A[v_local,k]*B[k,b].  A (=W) streamed directly from
// GMEM (zero reuse -> no smem, no barriers); B (=x) staged once in smem.
__global__ void __launch_bounds__(NTHREADS)
caps_mma_kernel(const float4* __restrict__ x4, const float* __restrict__ w) {
    __shared__ float Bsm[BB * BSTRIDE];   // 32 x 260 floats = 33.3 KB

    const int tid  = threadIdx.x;
    const int wrp  = tid >> 5;        // warp 0..7 -> m rows [wrp*16, wrp*16+16)
    const int lane = tid & 31;
    const int g    = lane >> 2;       // groupID 0..7
    const int t    = lane & 3;        // threadID-in-group 0..3
    const int v0   = blockIdx.x * VTILE;
    const int i0   = blockIdx.y * CTA_I;

    // ---- stage B once: x[b][i0..i0+32][0..8] -> Bsm[b][k], k=(i-i0)*8+d ----
    #pragma unroll
    for (int j = 0; j < 8; ++j) {
        const int t4 = tid + j * NTHREADS;   // 0..2047
        const int b  = t4 >> 6;              // 64 float4 per b-row
        const int kq = t4 & 63;
        cp_async16(&Bsm[b * BSTRIDE + kq * 4],
                   &x4[(size_t)b * 8192 + (size_t)i0 * 2 + kq]);
    }
    cp_commit();

    float c[4][4];
    #pragma unroll
    for (int nt = 0; nt < 4; ++nt)
        #pragma unroll
        for (int j = 0; j < 4; ++j) c[nt][j] = 0.f;

    const int row = wrp * 16 + g;                         // A row (v_local)
    const float* wp = w + ((size_t)i0 * 512 + v0 + row) * 8;  // W[i0][v0+row][0]

    cp_wait0();
    __syncthreads();   // the only barrier: B resident

    // ---- mainloop: 32 i's, K=8 each; no syncs, warps fully decoupled ----
    #pragma unroll 4
    for (int il = 0; il < CTA_I; ++il) {
        // A fragment direct from GMEM: rows row, row+8; cols t, t+4 (d-dim)
        const float* ap = wp + (size_t)il * 4096;   // W[i0+il][v0+row][0]
        float af[4] = { ap[t], ap[64 + t], ap[t + 4], ap[64 + t + 4] };
        uint32_t ah[4], al[4];
        #pragma unroll
        for (int j = 0; j < 4; ++j) {
            ah[j] = tf32_hi(af[j]);
            al[j] = tf32_lo(af[j], ah[j]);
        }
        #pragma unroll
        for (int nt = 0; nt < 4; ++nt) {
            // B fragment: col n = nt*8+g (b), rows k = il*8+t, +4
            const float* bp = &Bsm[(nt * 8 + g) * BSTRIDE + il * 8 + t];
            float bf0 = bp[0], bf1 = bp[4];
            uint32_t bh[2], bl[2];
            bh[0] = tf32_hi(bf0); bl[0] = tf32_lo(bf0, bh[0]);
            bh[1] = tf32_hi(bf1); bl[1] = tf32_lo(bf1, bh[1]);
            mma_tf32(c[nt], ah, bh);
            mma_tf32(c[nt], ah, bl);
            mma_tf32(c[nt], al, bh);
        }
    }

    // ---- epilogue: scatter accumulators to split-K partials ----
    float* outp = &g_part[blockIdx.y][0];
    #pragma unroll
    for (int nt = 0; nt < 4; ++nt) {
        const int bc = nt * 8 + t * 2;
        outp[(size_t)bc * VV + v0 + row]           = c[nt][0];
        outp[(size_t)(bc + 1) * VV + v0 + row]     = c[nt][1];
        outp[(size_t)bc * VV + v0 + row + 8]       = c[nt][2];
        outp[(size_t)(bc + 1) * VV + v0 + row + 8] = c[nt][3];
    }
}

// First-stage reduction: 256 blocks, each folds 16 chunks for one b.
__global__ void __launch_bounds__(256)
caps_reduce_kernel() {
    const int b   = blockIdx.x;   // 0..31
    const int s   = blockIdx.y;   // 0..NRED-1
    const int tid = threadIdx.x;
    #pragma unroll
    for (int j = 0; j < 2; ++j) {
        const int v = tid + j * 256;
        float acc = 0.f;
        #pragma unroll
        for (int cc = 0; cc < NCHUNK / NRED; ++cc)
            acc += g_part[s * (NCHUNK / NRED) + cc][b * VV + v];
        g_red[s][b * VV + v] = acc;
    }
}

// Final: fold NRED partials, squash, write (t, outputs) — identical halves.
__global__ void __launch_bounds__(256)
caps_finish_kernel(float* __restrict__ out, int out_size) {
    const int b   = blockIdx.x;
    const int tid = threadIdx.x;
    __shared__ float red[256];

    float local[2];
    #pragma unroll
    for (int j = 0; j < 2; ++j) {
        const int v = tid + j * 256;
        float acc = 0.f;
        #pragma unroll
        for (int cc = 0; cc < NRED; ++cc) acc += g_red[cc][b * VV + v];
        local[j] = acc;
    }

    float sq = local[0] * local[0] + local[1] * local[1];
    red[tid] = sq;
    __syncthreads();
    for (int off = 128; off; off >>= 1) {
        if (tid < off) red[tid] += red[tid + off];
        __syncthreads();
    }
    const float total = red[0];
    const float scale = total / ((1.0f + total) * sqrtf(total));

    #pragma unroll
    for (int j = 0; j < 2; ++j) {
        const int v   = tid + j * 256;
        const float o = local[j] * scale;
        const int idx = b * VV + v;
        if (idx < out_size) out[idx] = o;                       // t
        if (idx + BB * VV < out_size) out[idx + BB * VV] = o;   // outputs
    }
}

extern "C" void kernel_launch(void* const* d_in, const int* in_sizes, int n_in,
                              void* d_out, int out_size) {
    const float4* x4 = (const float4*)d_in[0];  // x: [32, 4096, 8] fp32
    const float*  w  = (const float*)d_in[1];   // W: [1, 4096, 512, 8] fp32
    float* out = (float*)d_out;

    dim3 grid1(VV / VTILE, NCHUNK);  // (4, 128) = 512 CTAs
    caps_mma_kernel<<<grid1, NTHREADS>>>(x4, w);
    caps_reduce_kernel<<<dim3(BB, NRED), 256>>>();
    caps_finish_kernel<<<BB, 256>>>(out, out_size);
}